// round 15
// baseline (speedup 1.0000x reference)
#include <cuda_runtime.h>
#include <cuda_bf16.h>
#include <cuda_fp16.h>
#include <math.h>
#include <stdint.h>

#define NN 20000
#define NE 640000
#define HD 4
#define CC 64
#define FO 256
#define NEG_SLOPE 0.2f

struct __align__(16) EdgeRec { int e; int s; float ea; float at; };

// ================= scratch =================
__device__ __align__(16) __half g_xh[(size_t)NN * FO];
__device__ __align__(16) __half g_hh[(size_t)NN * FO];   // layer-1 output, fp16 (GEMM2 input only)
__device__ float g_alpha_r[(size_t)NE * HD];   // overflow only (deg > 64)
__device__ EdgeRec g_edge_r[NE];
__device__ float g_asrc[NN * HD];
__device__ float g_adst[NN * HD];
__device__ float g_ce1[HD];
__device__ float g_ce2[HD];
__device__ int   g_cnt[NN];
__device__ int   g_cursor[NN];
__device__ int   g_rowstart[NN + 1];
__device__ __align__(16) __nv_bfloat16 g_Wt1hi[256 * 128];
__device__ __align__(16) __nv_bfloat16 g_Wt1lo[256 * 128];
__device__ __align__(16) __nv_bfloat16 g_Wt2hi[256 * 256];
__device__ __align__(16) __nv_bfloat16 g_Wt2lo[256 * 256];

// ---- packed f32x2 helpers (Blackwell FFMA2) ----
__device__ __forceinline__ uint64_t pack_f32x2(float lo, float hi) {
    uint64_t p;
    asm("mov.b64 %0, {%1, %2};" : "=l"(p) : "f"(lo), "f"(hi));
    return p;
}
__device__ __forceinline__ void unpack_f32x2(uint64_t p, float& lo, float& hi) {
    asm("mov.b64 {%0, %1}, %2;" : "=f"(lo), "=f"(hi) : "l"(p));
}
#define FMA2(acc, a, b) \
    asm("fma.rn.f32x2 %0, %1, %2, %0;" : "+l"(acc) : "l"(a), "l"(b))

// ================= CSR build =================
__global__ void zero_counts_kernel() {
    int i = blockIdx.x * blockDim.x + threadIdx.x;
    if (i < NN) { g_cnt[i] = 0; g_cursor[i] = 0; }
}

__global__ void hist_kernel(const int* __restrict__ dst) {
    int e = (blockIdx.x * blockDim.x + threadIdx.x) * 4;
    if (e + 3 < NE) {
        int4 d = *(const int4*)(dst + e);
        atomicAdd(&g_cnt[d.x], 1);
        atomicAdd(&g_cnt[d.y], 1);
        atomicAdd(&g_cnt[d.z], 1);
        atomicAdd(&g_cnt[d.w], 1);
    }
}

__global__ void scan_kernel(const float* __restrict__ We1, const float* __restrict__ ae1,
                            const float* __restrict__ We2, const float* __restrict__ ae2)
{
    int tid = threadIdx.x;
    int wq = tid >> 5, lane = tid & 31;
    if (wq < 8) {
        const float* We = (wq < 4) ? We1 : We2;
        const float* ae = (wq < 4) ? ae1 : ae2;
        float* ce = (wq < 4) ? g_ce1 : g_ce2;
        int h = wq & 3;
        float v = We[h * 64 + lane] * ae[h * 64 + lane]
                + We[h * 64 + lane + 32] * ae[h * 64 + lane + 32];
#pragma unroll
        for (int o = 16; o; o >>= 1) v += __shfl_xor_sync(0xffffffffu, v, o);
        if (lane == 0) ce[h] = v;
    }

    const int PER = 20;
    int base = tid * PER;
    int loc[PER];
    int sum = 0;
#pragma unroll
    for (int j = 0; j < PER; j++) {
        int i = base + j;
        int v = (i < NN) ? g_cnt[i] : 0;
        sum += v;
        loc[j] = sum;
    }
    int x = sum;
#pragma unroll
    for (int o = 1; o < 32; o <<= 1) {
        int t = __shfl_up_sync(0xffffffffu, x, o);
        if (lane >= o) x += t;
    }
    __shared__ int wsum[32];
    if (lane == 31) wsum[wq] = x;
    __syncthreads();
    if (wq == 0) {
        int y = (lane < 32) ? wsum[lane] : 0;
#pragma unroll
        for (int o = 1; o < 32; o <<= 1) {
            int t = __shfl_up_sync(0xffffffffu, y, o);
            if (lane >= o) y += t;
        }
        wsum[lane] = y;
    }
    __syncthreads();
    int excl = x - sum + (wq ? wsum[wq - 1] : 0);
    if (tid == 0) g_rowstart[0] = 0;
#pragma unroll
    for (int j = 0; j < PER; j++) {
        int i = base + j;
        if (i < NN) g_rowstart[i + 1] = excl + loc[j];
    }
}

__global__ void scatter_kernel(const int* __restrict__ src,
                               const int* __restrict__ dst,
                               const float* __restrict__ edge_attr,
                               const float* __restrict__ edge_atten)
{
    int e = (blockIdx.x * blockDim.x + threadIdx.x) * 2;
    if (e + 1 < NE) {
        int2   d2 = *(const int2*)(dst + e);
        int2   s2 = *(const int2*)(src + e);
        float2 ea = *(const float2*)(edge_attr + e);
        float2 at = *(const float2*)(edge_atten + e);
        int p0 = g_rowstart[d2.x] + atomicAdd(&g_cursor[d2.x], 1);
        int p1 = g_rowstart[d2.y] + atomicAdd(&g_cursor[d2.y], 1);
        EdgeRec r0 = {e, s2.x, ea.x, at.x};
        EdgeRec r1 = {e + 1, s2.y, ea.y, at.y};
        g_edge_r[p0] = r0;
        g_edge_r[p1] = r1;
    }
}

// ================= W transpose + bf16 split =================
__global__ void convert_w_kernel(const float* __restrict__ W1,
                                 const float* __restrict__ W2,
                                 __nv_bfloat16* __restrict__ W1hi,
                                 __nv_bfloat16* __restrict__ W1lo,
                                 __nv_bfloat16* __restrict__ W2hi,
                                 __nv_bfloat16* __restrict__ W2lo)
{
    int idx = blockIdx.x * blockDim.x + threadIdx.x;
    if (idx < 128 * 256) {
        int k = idx >> 8, n = idx & 255;
        float v = W1[idx];
        __nv_bfloat16 h = __float2bfloat16_rn(v);
        W1hi[n * 128 + k] = h;
        W1lo[n * 128 + k] = __float2bfloat16_rn(v - __bfloat162float(h));
    } else if (idx < 128 * 256 + 256 * 256) {
        int i2 = idx - 128 * 256;
        int k = i2 >> 8, n = i2 & 255;
        float v = W2[i2];
        __nv_bfloat16 h = __float2bfloat16_rn(v);
        W2hi[n * 256 + k] = h;
        W2lo[n * 256 + k] = __float2bfloat16_rn(v - __bfloat162float(h));
    }
}

// ================= split-bf16 mma.sync GEMM + fused alpha dots =================
__device__ __forceinline__ void mma_bf16(float* c, uint32_t a0, uint32_t a1,
                                         uint32_t a2, uint32_t a3,
                                         uint32_t b0, uint32_t b1)
{
    asm volatile(
        "mma.sync.aligned.m16n8k16.row.col.f32.bf16.bf16.f32 "
        "{%0,%1,%2,%3}, {%4,%5,%6,%7}, {%8,%9}, {%0,%1,%2,%3};"
        : "+f"(c[0]), "+f"(c[1]), "+f"(c[2]), "+f"(c[3])
        : "r"(a0), "r"(a1), "r"(a2), "r"(a3), "r"(b0), "r"(b1));
}

#define KP 20

template<bool A_HALF>
__global__ __launch_bounds__(256) void gemm_mma_kernel(
    const void* __restrict__ Avoid,
    const __nv_bfloat16* __restrict__ Bhi,
    const __nv_bfloat16* __restrict__ Blo,
    __half* __restrict__ C, int K,
    const float* __restrict__ asrc, const float* __restrict__ adst)
{
    __shared__ uint32_t As_hi[128][KP];
    __shared__ uint32_t As_lo[128][KP];
    __shared__ uint32_t Bs_hi[128][KP];
    __shared__ uint32_t Bs_lo[128][KP];

    int tid = threadIdx.x;
    int wid = tid >> 5, lane = tid & 31;
    int m0c = blockIdx.x * 128, n0c = blockIdx.y * 128;
    int wm0 = (wid >> 1) * 32, wn0 = (wid & 1) * 64;
    int lq = lane >> 2, lr = lane & 3;

    float acc[2][8][4];
#pragma unroll
    for (int mt = 0; mt < 2; mt++)
#pragma unroll
        for (int nt = 0; nt < 8; nt++)
#pragma unroll
            for (int j = 0; j < 4; j++) acc[mt][nt][j] = 0.f;

    int a_row = tid >> 1, a_half = tid & 1;
    int a_grow = m0c + a_row;
    bool a_ok = (a_grow < NN);
    int b_row = tid & 127, b_half = tid >> 7;

    const float*  Abf = (const float*)Avoid + (size_t)a_grow * K + a_half * 16;
    const __half* Abh = (const __half*)Avoid + (size_t)a_grow * K + a_half * 16;
    const __nv_bfloat16* Bhbase = Bhi + (size_t)(n0c + b_row) * K + b_half * 16;
    const __nv_bfloat16* Blbase = Blo + (size_t)(n0c + b_row) * K + b_half * 16;

    auto loadA = [&](int off, int j) -> float4 {
        if (!a_ok) return make_float4(0.f, 0.f, 0.f, 0.f);
        if (A_HALF) {
            uint2 raw = *(const uint2*)(Abh + off + j * 4);
            float2 x0 = __half22float2(*(__half2*)&raw.x);
            float2 x1 = __half22float2(*(__half2*)&raw.y);
            return make_float4(x0.x, x0.y, x1.x, x1.y);
        } else {
            return *(const float4*)(Abf + off + j * 4);
        }
    };

    float4 av[4];
    uint4 bvh0, bvh1, bvl0, bvl1;
#pragma unroll
    for (int j = 0; j < 4; j++) av[j] = loadA(0, j);
    bvh0 = *(const uint4*)(Bhbase);
    bvh1 = *(const uint4*)(Bhbase + 8);
    bvl0 = *(const uint4*)(Blbase);
    bvl1 = *(const uint4*)(Blbase + 8);

    int nchunks = K >> 5;
    for (int c = 0; c < nchunks; c++) {
#pragma unroll
        for (int j = 0; j < 4; j++) {
            float4 v = av[j];
            __nv_bfloat162 h01 = __floats2bfloat162_rn(v.x, v.y);
            __nv_bfloat162 h23 = __floats2bfloat162_rn(v.z, v.w);
            __nv_bfloat162 l01 = __floats2bfloat162_rn(v.x - __low2float(h01),
                                                       v.y - __high2float(h01));
            __nv_bfloat162 l23 = __floats2bfloat162_rn(v.z - __low2float(h23),
                                                       v.w - __high2float(h23));
            int ci = (a_half * 16 + j * 4) >> 1;
            As_hi[a_row][ci]     = *(uint32_t*)&h01;
            As_hi[a_row][ci + 1] = *(uint32_t*)&h23;
            As_lo[a_row][ci]     = *(uint32_t*)&l01;
            As_lo[a_row][ci + 1] = *(uint32_t*)&l23;
        }
        {
            int ci = b_half * 8;
            *(uint4*)&Bs_hi[b_row][ci]     = bvh0;
            *(uint4*)&Bs_hi[b_row][ci + 4] = bvh1;
            *(uint4*)&Bs_lo[b_row][ci]     = bvl0;
            *(uint4*)&Bs_lo[b_row][ci + 4] = bvl1;
        }
        __syncthreads();

        if (c + 1 < nchunks) {
            int k0 = (c + 1) << 5;
#pragma unroll
            for (int j = 0; j < 4; j++) av[j] = loadA(k0, j);
            bvh0 = *(const uint4*)(Bhbase + k0);
            bvh1 = *(const uint4*)(Bhbase + k0 + 8);
            bvl0 = *(const uint4*)(Blbase + k0);
            bvl1 = *(const uint4*)(Blbase + k0 + 8);
        }

#pragma unroll
        for (int ks = 0; ks < 2; ks++) {
            int kb = ks * 8 + lr;
            uint32_t ah[2][4], al[2][4];
#pragma unroll
            for (int mt = 0; mt < 2; mt++) {
                int ra = wm0 + mt * 16 + lq, rb = ra + 8;
                ah[mt][0] = As_hi[ra][kb];     ah[mt][1] = As_hi[rb][kb];
                ah[mt][2] = As_hi[ra][kb + 4]; ah[mt][3] = As_hi[rb][kb + 4];
                al[mt][0] = As_lo[ra][kb];     al[mt][1] = As_lo[rb][kb];
                al[mt][2] = As_lo[ra][kb + 4]; al[mt][3] = As_lo[rb][kb + 4];
            }
#pragma unroll
            for (int nt = 0; nt < 8; nt++) {
                int nr = wn0 + nt * 8 + lq;
                uint32_t bh0 = Bs_hi[nr][kb], bh1 = Bs_hi[nr][kb + 4];
                uint32_t bl0 = Bs_lo[nr][kb], bl1 = Bs_lo[nr][kb + 4];
#pragma unroll
                for (int mt = 0; mt < 2; mt++) {
                    mma_bf16(acc[mt][nt], ah[mt][0], ah[mt][1], ah[mt][2], ah[mt][3], bh0, bh1);
                    mma_bf16(acc[mt][nt], ah[mt][0], ah[mt][1], ah[mt][2], ah[mt][3], bl0, bl1);
                    mma_bf16(acc[mt][nt], al[mt][0], al[mt][1], al[mt][2], al[mt][3], bh0, bh1);
                }
            }
        }
        __syncthreads();
    }

    // ---- C store (fp16) ----
#pragma unroll
    for (int mt = 0; mt < 2; mt++) {
        int row0 = m0c + wm0 + mt * 16 + lq;
#pragma unroll
        for (int nt = 0; nt < 8; nt++) {
            int col = n0c + wn0 + nt * 8 + 2 * lr;
            if (row0 < NN)
                *(__half2*)(C + (size_t)row0 * FO + col) =
                    __floats2half2_rn(acc[mt][nt][0], acc[mt][nt][1]);
            if (row0 + 8 < NN)
                *(__half2*)(C + (size_t)(row0 + 8) * FO + col) =
                    __floats2half2_rn(acc[mt][nt][2], acc[mt][nt][3]);
        }
    }

    // ---- fused alpha_src / alpha_dst ----
    {
        int h = (n0c + wn0) >> 6;
        float ps0 = 0.f, ps1 = 0.f, ps2 = 0.f, ps3 = 0.f;
        float pd0 = 0.f, pd1 = 0.f, pd2 = 0.f, pd3 = 0.f;
#pragma unroll
        for (int nt = 0; nt < 8; nt++) {
            int c0 = nt * 8 + 2 * lr;
            float2 cs = *(const float2*)(asrc + h * 64 + c0);
            float2 cd = *(const float2*)(adst + h * 64 + c0);
            ps0 += acc[0][nt][0] * cs.x + acc[0][nt][1] * cs.y;
            ps1 += acc[0][nt][2] * cs.x + acc[0][nt][3] * cs.y;
            ps2 += acc[1][nt][0] * cs.x + acc[1][nt][1] * cs.y;
            ps3 += acc[1][nt][2] * cs.x + acc[1][nt][3] * cs.y;
            pd0 += acc[0][nt][0] * cd.x + acc[0][nt][1] * cd.y;
            pd1 += acc[0][nt][2] * cd.x + acc[0][nt][3] * cd.y;
            pd2 += acc[1][nt][0] * cd.x + acc[1][nt][1] * cd.y;
            pd3 += acc[1][nt][2] * cd.x + acc[1][nt][3] * cd.y;
        }
#pragma unroll
        for (int o = 1; o <= 2; o <<= 1) {
            ps0 += __shfl_xor_sync(0xffffffffu, ps0, o);
            ps1 += __shfl_xor_sync(0xffffffffu, ps1, o);
            ps2 += __shfl_xor_sync(0xffffffffu, ps2, o);
            ps3 += __shfl_xor_sync(0xffffffffu, ps3, o);
            pd0 += __shfl_xor_sync(0xffffffffu, pd0, o);
            pd1 += __shfl_xor_sync(0xffffffffu, pd1, o);
            pd2 += __shfl_xor_sync(0xffffffffu, pd2, o);
            pd3 += __shfl_xor_sync(0xffffffffu, pd3, o);
        }
        if (lr == 0) {
            int r = m0c + wm0 + lq;
            if (r < NN)      { g_asrc[r * 4 + h] = ps0;        g_adst[r * 4 + h] = pd0; }
            if (r + 8 < NN)  { g_asrc[(r + 8) * 4 + h] = ps1;  g_adst[(r + 8) * 4 + h] = pd1; }
            if (r + 16 < NN) { g_asrc[(r + 16) * 4 + h] = ps2; g_adst[(r + 16) * 4 + h] = pd2; }
            if (r + 24 < NN) { g_asrc[(r + 24) * 4 + h] = ps3; g_adst[(r + 24) * 4 + h] = pd3; }
        }
    }
}

// ================= fused: logits + softmax + fp16 gather, warp per dst ==========
// Alphas + EdgeRec for the first 2 strided iterations (deg<=64) live in registers.
template<bool OUT_HALF>
__global__ __launch_bounds__(256) void fused_agg_kernel(
    const float* __restrict__ ce,
    const float* __restrict__ bias,
    void* __restrict__ out_h,
    float* __restrict__ out_w)
{
    __shared__ float s_w[8][32][4];
    __shared__ int   s_s[8][32];
    int wslot = threadIdx.x >> 5;
    int n = blockIdx.x * 8 + wslot;
    int lane = threadIdx.x & 31;
    if (n >= NN) return;
    int r0 = g_rowstart[n], r1 = g_rowstart[n + 1];

    float4 c   = *(const float4*)ce;
    float4 adn = *(const float4*)(g_adst + (size_t)n * 4);

    float4 exA = make_float4(0.f, 0.f, 0.f, 0.f);
    float4 exB = make_float4(0.f, 0.f, 0.f, 0.f);
    int   sA = 0, sB = 0, eA = 0, eB = 0;
    float atA = 0.f, atB = 0.f;

    // ---- pass 1: logits + leaky relu + max ----
    float mx0 = -3.4e38f, mx1 = -3.4e38f, mx2 = -3.4e38f, mx3 = -3.4e38f;
    {
        int it = 0;
        for (int i = r0 + lane; i < r1; i += 32, it++) {
            EdgeRec er = g_edge_r[i];
            float4 as = *(const float4*)(g_asrc + (size_t)er.s * 4);
            float a0 = as.x + adn.x + er.ea * c.x;
            float a1 = as.y + adn.y + er.ea * c.y;
            float a2 = as.z + adn.z + er.ea * c.z;
            float a3 = as.w + adn.w + er.ea * c.w;
            a0 = a0 > 0.f ? a0 : NEG_SLOPE * a0;
            a1 = a1 > 0.f ? a1 : NEG_SLOPE * a1;
            a2 = a2 > 0.f ? a2 : NEG_SLOPE * a2;
            a3 = a3 > 0.f ? a3 : NEG_SLOPE * a3;
            if (it == 0) {
                exA = make_float4(a0, a1, a2, a3);
                sA = er.s; eA = er.e; atA = er.at;
            } else if (it == 1) {
                exB = make_float4(a0, a1, a2, a3);
                sB = er.s; eB = er.e; atB = er.at;
            } else {
                *(float4*)(g_alpha_r + (size_t)i * 4) = make_float4(a0, a1, a2, a3);
            }
            mx0 = fmaxf(mx0, a0); mx1 = fmaxf(mx1, a1);
            mx2 = fmaxf(mx2, a2); mx3 = fmaxf(mx3, a3);
        }
    }
#pragma unroll
    for (int o = 16; o; o >>= 1) {
        mx0 = fmaxf(mx0, __shfl_xor_sync(0xffffffffu, mx0, o));
        mx1 = fmaxf(mx1, __shfl_xor_sync(0xffffffffu, mx1, o));
        mx2 = fmaxf(mx2, __shfl_xor_sync(0xffffffffu, mx2, o));
        mx3 = fmaxf(mx3, __shfl_xor_sync(0xffffffffu, mx3, o));
    }

    // ---- pass 2: exp + denom ----
    float dn0 = 0.f, dn1 = 0.f, dn2 = 0.f, dn3 = 0.f;
    {
        int it = 0;
        for (int i = r0 + lane; i < r1; i += 32, it++) {
            float4 a = (it == 0) ? exA : (it == 1) ? exB
                                       : *(const float4*)(g_alpha_r + (size_t)i * 4);
            float e0 = __expf(a.x - mx0), e1 = __expf(a.y - mx1);
            float e2 = __expf(a.z - mx2), e3 = __expf(a.w - mx3);
            if (it == 0)      exA = make_float4(e0, e1, e2, e3);
            else if (it == 1) exB = make_float4(e0, e1, e2, e3);
            else *(float4*)(g_alpha_r + (size_t)i * 4) = make_float4(e0, e1, e2, e3);
            dn0 += e0; dn1 += e1; dn2 += e2; dn3 += e3;
        }
    }
#pragma unroll
    for (int o = 16; o; o >>= 1) {
        dn0 += __shfl_xor_sync(0xffffffffu, dn0, o);
        dn1 += __shfl_xor_sync(0xffffffffu, dn1, o);
        dn2 += __shfl_xor_sync(0xffffffffu, dn2, o);
        dn3 += __shfl_xor_sync(0xffffffffu, dn3, o);
    }
    float inv0 = 1.f / (dn0 + 1e-16f);
    float inv1 = 1.f / (dn1 + 1e-16f);
    float inv2 = 1.f / (dn2 + 1e-16f);
    float inv3 = 1.f / (dn3 + 1e-16f);

    // ---- pass 3: weights + fp16 gather with packed f32x2 FMA ----
    int hsel = lane >> 3;
    uint64_t ac0 = pack_f32x2(0.f, 0.f);
    uint64_t ac1 = ac0, ac2 = ac0, ac3 = ac0;

    int chunk = 0;
    for (int base = r0; base < r1; base += 32, chunk++) {
        int i = base + lane;
        int cnt = min(32, r1 - base);
        if (i < r1) {
            float4 ex;
            int e_, s_;
            float at_;
            if (chunk == 0)      { ex = exA; e_ = eA; s_ = sA; at_ = atA; }
            else if (chunk == 1) { ex = exB; e_ = eB; s_ = sB; at_ = atB; }
            else {
                ex = *(const float4*)(g_alpha_r + (size_t)i * 4);
                EdgeRec er = g_edge_r[i];
                e_ = er.e; s_ = er.s; at_ = er.at;
            }
            float w0 = ex.x * inv0, w1 = ex.y * inv1;
            float w2 = ex.z * inv2, w3 = ex.w * inv3;
            *(float4*)(out_w + (size_t)e_ * 4) = make_float4(w0, w1, w2, w3);
            *(float4*)&s_w[wslot][lane][0] =
                make_float4(w0 * at_, w1 * at_, w2 * at_, w3 * at_);
            s_s[wslot][lane] = s_;
        }
        __syncwarp();
        for (int j = 0; j < cnt; j++) {
            float w = s_w[wslot][j][hsel];
            uint64_t wp = pack_f32x2(w, w);
            int sc = s_s[wslot][j];
            uint4 v = *((const uint4*)(g_xh + (size_t)sc * FO) + lane);
            float2 f0 = __half22float2(*(__half2*)&v.x);
            float2 f1 = __half22float2(*(__half2*)&v.y);
            float2 f2 = __half22float2(*(__half2*)&v.z);
            float2 f3 = __half22float2(*(__half2*)&v.w);
            uint64_t p0 = pack_f32x2(f0.x, f0.y);
            uint64_t p1 = pack_f32x2(f1.x, f1.y);
            uint64_t p2 = pack_f32x2(f2.x, f2.y);
            uint64_t p3 = pack_f32x2(f3.x, f3.y);
            FMA2(ac0, p0, wp);
            FMA2(ac1, p1, wp);
            FMA2(ac2, p2, wp);
            FMA2(ac3, p3, wp);
        }
        __syncwarp();
    }

    float o0, o1, o2, o3, o4, o5, o6, o7;
    unpack_f32x2(ac0, o0, o1);
    unpack_f32x2(ac1, o2, o3);
    unpack_f32x2(ac2, o4, o5);
    unpack_f32x2(ac3, o6, o7);

    float4 bA = *(const float4*)(bias + lane * 8);
    float4 bB = *(const float4*)(bias + lane * 8 + 4);
    o0 += bA.x; o1 += bA.y; o2 += bA.z; o3 += bA.w;
    o4 += bB.x; o5 += bB.y; o6 += bB.z; o7 += bB.w;

    if (OUT_HALF) {
        __half* orow = (__half*)out_h + (size_t)n * FO + lane * 8;
        uint4 pk;
        __half2 h0 = __floats2half2_rn(o0, o1);
        __half2 h1 = __floats2half2_rn(o2, o3);
        __half2 h2 = __floats2half2_rn(o4, o5);
        __half2 h3 = __floats2half2_rn(o6, o7);
        pk.x = *(uint32_t*)&h0; pk.y = *(uint32_t*)&h1;
        pk.z = *(uint32_t*)&h2; pk.w = *(uint32_t*)&h3;
        *(uint4*)orow = pk;
    } else {
        float* orow = (float*)out_h + (size_t)n * FO + lane * 8;
        *(float4*)orow = make_float4(o0, o1, o2, o3);
        *(float4*)(orow + 4) = make_float4(o4, o5, o6, o7);
    }
}

// ================= launch =================
extern "C" void kernel_launch(void* const* d_in, const int* in_sizes, int n_in,
                              void* d_out, int out_size)
{
    const float* x          = (const float*)d_in[0];
    const int*   edge_index = (const int*)d_in[1];
    const float* edge_attr  = (const float*)d_in[3];
    const float* edge_atten = (const float*)d_in[4];
    const float* W1    = (const float*)d_in[5];
    const float* asrc1 = (const float*)d_in[6];
    const float* adst1 = (const float*)d_in[7];
    const float* We1   = (const float*)d_in[8];
    const float* ae1   = (const float*)d_in[9];
    const float* b1    = (const float*)d_in[10];
    const float* W2    = (const float*)d_in[11];
    const float* asrc2 = (const float*)d_in[12];
    const float* adst2 = (const float*)d_in[13];
    const float* We2   = (const float*)d_in[14];
    const float* ae2   = (const float*)d_in[15];
    const float* b2    = (const float*)d_in[16];

    const int* src = edge_index;
    const int* dst = edge_index + NE;

    float* out    = (float*)d_out;
    float* out_h  = out;
    float* out_w1 = out + (size_t)NN * FO;
    float* out_w2 = out_w1 + (size_t)NE * HD;

    __half* xh;  cudaGetSymbolAddress((void**)&xh, g_xh);
    __half* hh;  cudaGetSymbolAddress((void**)&hh, g_hh);
    float* ce1;  cudaGetSymbolAddress((void**)&ce1, g_ce1);
    float* ce2;  cudaGetSymbolAddress((void**)&ce2, g_ce2);
    __nv_bfloat16 *wt1h, *wt1l, *wt2h, *wt2l;
    cudaGetSymbolAddress((void**)&wt1h, g_Wt1hi);
    cudaGetSymbolAddress((void**)&wt1l, g_Wt1lo);
    cudaGetSymbolAddress((void**)&wt2h, g_Wt2hi);
    cudaGetSymbolAddress((void**)&wt2l, g_Wt2lo);

    // setup: CSR + ce + W conversion
    zero_counts_kernel<<<(NN + 255) / 256, 256>>>();
    hist_kernel<<<(NE / 4 + 255) / 256, 256>>>(dst);
    scan_kernel<<<1, 1024>>>(We1, ae1, We2, ae2);
    scatter_kernel<<<(NE / 2 + 255) / 256, 256>>>(src, dst, edge_attr, edge_atten);
    convert_w_kernel<<<(128 * 256 + 256 * 256 + 255) / 256, 256>>>(W1, W2, wt1h, wt1l, wt2h, wt2l);

    dim3 ggrid((NN + 127) / 128, 2);
    // layer 1: fp32 x -> xh fp16; h -> g_hh fp16
    gemm_mma_kernel<false><<<ggrid, 256>>>(x, wt1h, wt1l, xh, 128, asrc1, adst1);
    fused_agg_kernel<true><<<(NN + 7) / 8, 256>>>(ce1, b1, hh, out_w1);
    // layer 2: fp16 h -> xh fp16; h -> out_h fp32
    gemm_mma_kernel<true><<<ggrid, 256>>>(hh, wt2h, wt2l, xh, 256, asrc2, adst2);
    fused_agg_kernel<false><<<(NN + 7) / 8, 256>>>(ce2, b2, out_h, out_w2);
}

// round 16
// speedup vs baseline: 1.1627x; 1.1627x over previous
#include <cuda_runtime.h>
#include <cuda_bf16.h>
#include <cuda_fp16.h>
#include <math.h>
#include <stdint.h>

#define NN 20000
#define NE 640000
#define HD 4
#define CC 64
#define FO 256
#define NEG_SLOPE 0.2f

struct __align__(16) EdgeRec { int e; int s; float ea; float at; };

// ================= scratch =================
__device__ __align__(16) __half g_xh[(size_t)NN * FO];
__device__ float g_h[(size_t)NN * FO];
__device__ float g_alpha_r[(size_t)NE * HD];   // overflow only (deg > 64)
__device__ EdgeRec g_edge_r[NE];
__device__ float g_asrc[NN * HD];
__device__ float g_adst[NN * HD];
__device__ float g_ce1[HD];
__device__ float g_ce2[HD];
__device__ int   g_cnt[NN];
__device__ int   g_cursor[NN];
__device__ int   g_rowstart[NN + 1];
__device__ __align__(16) __nv_bfloat16 g_Wt1hi[256 * 128];
__device__ __align__(16) __nv_bfloat16 g_Wt1lo[256 * 128];
__device__ __align__(16) __nv_bfloat16 g_Wt2hi[256 * 256];
__device__ __align__(16) __nv_bfloat16 g_Wt2lo[256 * 256];

// ---- packed f32x2 helpers (Blackwell FFMA2) ----
__device__ __forceinline__ uint64_t pack_f32x2(float lo, float hi) {
    uint64_t p;
    asm("mov.b64 %0, {%1, %2};" : "=l"(p) : "f"(lo), "f"(hi));
    return p;
}
__device__ __forceinline__ void unpack_f32x2(uint64_t p, float& lo, float& hi) {
    asm("mov.b64 {%0, %1}, %2;" : "=f"(lo), "=f"(hi) : "l"(p));
}
#define FMA2(acc, a, b) \
    asm("fma.rn.f32x2 %0, %1, %2, %0;" : "+l"(acc) : "l"(a), "l"(b))

// ================= CSR build =================
__global__ void zero_counts_kernel() {
    int i = blockIdx.x * blockDim.x + threadIdx.x;
    if (i < NN) { g_cnt[i] = 0; g_cursor[i] = 0; }
}

__global__ void hist_kernel(const int* __restrict__ dst) {
    int e = (blockIdx.x * blockDim.x + threadIdx.x) * 4;
    if (e + 3 < NE) {
        int4 d = *(const int4*)(dst + e);
        atomicAdd(&g_cnt[d.x], 1);
        atomicAdd(&g_cnt[d.y], 1);
        atomicAdd(&g_cnt[d.z], 1);
        atomicAdd(&g_cnt[d.w], 1);
    }
}

__global__ void scan_kernel(const float* __restrict__ We1, const float* __restrict__ ae1,
                            const float* __restrict__ We2, const float* __restrict__ ae2)
{
    int tid = threadIdx.x;
    int wq = tid >> 5, lane = tid & 31;
    if (wq < 8) {
        const float* We = (wq < 4) ? We1 : We2;
        const float* ae = (wq < 4) ? ae1 : ae2;
        float* ce = (wq < 4) ? g_ce1 : g_ce2;
        int h = wq & 3;
        float v = We[h * 64 + lane] * ae[h * 64 + lane]
                + We[h * 64 + lane + 32] * ae[h * 64 + lane + 32];
#pragma unroll
        for (int o = 16; o; o >>= 1) v += __shfl_xor_sync(0xffffffffu, v, o);
        if (lane == 0) ce[h] = v;
    }

    const int PER = 20;
    int base = tid * PER;
    int loc[PER];
    int sum = 0;
#pragma unroll
    for (int j = 0; j < PER; j++) {
        int i = base + j;
        int v = (i < NN) ? g_cnt[i] : 0;
        sum += v;
        loc[j] = sum;
    }
    int x = sum;
#pragma unroll
    for (int o = 1; o < 32; o <<= 1) {
        int t = __shfl_up_sync(0xffffffffu, x, o);
        if (lane >= o) x += t;
    }
    __shared__ int wsum[32];
    if (lane == 31) wsum[wq] = x;
    __syncthreads();
    if (wq == 0) {
        int y = (lane < 32) ? wsum[lane] : 0;
#pragma unroll
        for (int o = 1; o < 32; o <<= 1) {
            int t = __shfl_up_sync(0xffffffffu, y, o);
            if (lane >= o) y += t;
        }
        wsum[lane] = y;
    }
    __syncthreads();
    int excl = x - sum + (wq ? wsum[wq - 1] : 0);
    if (tid == 0) g_rowstart[0] = 0;
#pragma unroll
    for (int j = 0; j < PER; j++) {
        int i = base + j;
        if (i < NN) g_rowstart[i + 1] = excl + loc[j];
    }
}

// scatter: CSR-ordered EdgeRec stream, ILP-2 (measured best)
__global__ void scatter_kernel(const int* __restrict__ src,
                               const int* __restrict__ dst,
                               const float* __restrict__ edge_attr,
                               const float* __restrict__ edge_atten)
{
    int e = (blockIdx.x * blockDim.x + threadIdx.x) * 2;
    if (e + 1 < NE) {
        int2   d2 = *(const int2*)(dst + e);
        int2   s2 = *(const int2*)(src + e);
        float2 ea = *(const float2*)(edge_attr + e);
        float2 at = *(const float2*)(edge_atten + e);
        int p0 = g_rowstart[d2.x] + atomicAdd(&g_cursor[d2.x], 1);
        int p1 = g_rowstart[d2.y] + atomicAdd(&g_cursor[d2.y], 1);
        EdgeRec r0 = {e, s2.x, ea.x, at.x};
        EdgeRec r1 = {e + 1, s2.y, ea.y, at.y};
        g_edge_r[p0] = r0;
        g_edge_r[p1] = r1;
    }
}

// ================= W transpose + bf16 split =================
__global__ void convert_w_kernel(const float* __restrict__ W1,
                                 const float* __restrict__ W2,
                                 __nv_bfloat16* __restrict__ W1hi,
                                 __nv_bfloat16* __restrict__ W1lo,
                                 __nv_bfloat16* __restrict__ W2hi,
                                 __nv_bfloat16* __restrict__ W2lo)
{
    int idx = blockIdx.x * blockDim.x + threadIdx.x;
    if (idx < 128 * 256) {
        int k = idx >> 8, n = idx & 255;
        float v = W1[idx];
        __nv_bfloat16 h = __float2bfloat16_rn(v);
        W1hi[n * 128 + k] = h;
        W1lo[n * 128 + k] = __float2bfloat16_rn(v - __bfloat162float(h));
    } else if (idx < 128 * 256 + 256 * 256) {
        int i2 = idx - 128 * 256;
        int k = i2 >> 8, n = i2 & 255;
        float v = W2[i2];
        __nv_bfloat16 h = __float2bfloat16_rn(v);
        W2hi[n * 256 + k] = h;
        W2lo[n * 256 + k] = __float2bfloat16_rn(v - __bfloat162float(h));
    }
}

// ================= split-bf16 mma.sync GEMM + fused alpha dots =================
__device__ __forceinline__ void mma_bf16(float* c, uint32_t a0, uint32_t a1,
                                         uint32_t a2, uint32_t a3,
                                         uint32_t b0, uint32_t b1)
{
    asm volatile(
        "mma.sync.aligned.m16n8k16.row.col.f32.bf16.bf16.f32 "
        "{%0,%1,%2,%3}, {%4,%5,%6,%7}, {%8,%9}, {%0,%1,%2,%3};"
        : "+f"(c[0]), "+f"(c[1]), "+f"(c[2]), "+f"(c[3])
        : "r"(a0), "r"(a1), "r"(a2), "r"(a3), "r"(b0), "r"(b1));
}

#define KP 20

__global__ __launch_bounds__(256) void gemm_mma_kernel(
    const float* __restrict__ A,
    const __nv_bfloat16* __restrict__ Bhi,
    const __nv_bfloat16* __restrict__ Blo,
    __half* __restrict__ C, int K,
    const float* __restrict__ asrc, const float* __restrict__ adst)
{
    __shared__ uint32_t As_hi[128][KP];
    __shared__ uint32_t As_lo[128][KP];
    __shared__ uint32_t Bs_hi[128][KP];
    __shared__ uint32_t Bs_lo[128][KP];

    int tid = threadIdx.x;
    int wid = tid >> 5, lane = tid & 31;
    int m0c = blockIdx.x * 128, n0c = blockIdx.y * 128;
    int wm0 = (wid >> 1) * 32, wn0 = (wid & 1) * 64;
    int lq = lane >> 2, lr = lane & 3;

    float acc[2][8][4];
#pragma unroll
    for (int mt = 0; mt < 2; mt++)
#pragma unroll
        for (int nt = 0; nt < 8; nt++)
#pragma unroll
            for (int j = 0; j < 4; j++) acc[mt][nt][j] = 0.f;

    int a_row = tid >> 1, a_half = tid & 1;
    int a_grow = m0c + a_row;
    bool a_ok = (a_grow < NN);
    int b_row = tid & 127, b_half = tid >> 7;

    const float* Abase = A + (size_t)a_grow * K + a_half * 16;
    const __nv_bfloat16* Bhbase = Bhi + (size_t)(n0c + b_row) * K + b_half * 16;
    const __nv_bfloat16* Blbase = Blo + (size_t)(n0c + b_row) * K + b_half * 16;

    float4 av[4];
    uint4 bvh0, bvh1, bvl0, bvl1;
#pragma unroll
    for (int j = 0; j < 4; j++)
        av[j] = a_ok ? *(const float4*)(Abase + j * 4)
                     : make_float4(0.f, 0.f, 0.f, 0.f);
    bvh0 = *(const uint4*)(Bhbase);
    bvh1 = *(const uint4*)(Bhbase + 8);
    bvl0 = *(const uint4*)(Blbase);
    bvl1 = *(const uint4*)(Blbase + 8);

    int nchunks = K >> 5;
    for (int c = 0; c < nchunks; c++) {
#pragma unroll
        for (int j = 0; j < 4; j++) {
            float4 v = av[j];
            __nv_bfloat162 h01 = __floats2bfloat162_rn(v.x, v.y);
            __nv_bfloat162 h23 = __floats2bfloat162_rn(v.z, v.w);
            __nv_bfloat162 l01 = __floats2bfloat162_rn(v.x - __low2float(h01),
                                                       v.y - __high2float(h01));
            __nv_bfloat162 l23 = __floats2bfloat162_rn(v.z - __low2float(h23),
                                                       v.w - __high2float(h23));
            int ci = (a_half * 16 + j * 4) >> 1;
            As_hi[a_row][ci]     = *(uint32_t*)&h01;
            As_hi[a_row][ci + 1] = *(uint32_t*)&h23;
            As_lo[a_row][ci]     = *(uint32_t*)&l01;
            As_lo[a_row][ci + 1] = *(uint32_t*)&l23;
        }
        {
            int ci = b_half * 8;
            *(uint4*)&Bs_hi[b_row][ci]     = bvh0;
            *(uint4*)&Bs_hi[b_row][ci + 4] = bvh1;
            *(uint4*)&Bs_lo[b_row][ci]     = bvl0;
            *(uint4*)&Bs_lo[b_row][ci + 4] = bvl1;
        }
        __syncthreads();

        if (c + 1 < nchunks) {
            int k0 = (c + 1) << 5;
#pragma unroll
            for (int j = 0; j < 4; j++)
                av[j] = a_ok ? *(const float4*)(Abase + k0 + j * 4)
                             : make_float4(0.f, 0.f, 0.f, 0.f);
            bvh0 = *(const uint4*)(Bhbase + k0);
            bvh1 = *(const uint4*)(Bhbase + k0 + 8);
            bvl0 = *(const uint4*)(Blbase + k0);
            bvl1 = *(const uint4*)(Blbase + k0 + 8);
        }

#pragma unroll
        for (int ks = 0; ks < 2; ks++) {
            int kb = ks * 8 + lr;
            uint32_t ah[2][4], al[2][4];
#pragma unroll
            for (int mt = 0; mt < 2; mt++) {
                int ra = wm0 + mt * 16 + lq, rb = ra + 8;
                ah[mt][0] = As_hi[ra][kb];     ah[mt][1] = As_hi[rb][kb];
                ah[mt][2] = As_hi[ra][kb + 4]; ah[mt][3] = As_hi[rb][kb + 4];
                al[mt][0] = As_lo[ra][kb];     al[mt][1] = As_lo[rb][kb];
                al[mt][2] = As_lo[ra][kb + 4]; al[mt][3] = As_lo[rb][kb + 4];
            }
#pragma unroll
            for (int nt = 0; nt < 8; nt++) {
                int nr = wn0 + nt * 8 + lq;
                uint32_t bh0 = Bs_hi[nr][kb], bh1 = Bs_hi[nr][kb + 4];
                uint32_t bl0 = Bs_lo[nr][kb], bl1 = Bs_lo[nr][kb + 4];
#pragma unroll
                for (int mt = 0; mt < 2; mt++) {
                    mma_bf16(acc[mt][nt], ah[mt][0], ah[mt][1], ah[mt][2], ah[mt][3], bh0, bh1);
                    mma_bf16(acc[mt][nt], ah[mt][0], ah[mt][1], ah[mt][2], ah[mt][3], bl0, bl1);
                    mma_bf16(acc[mt][nt], al[mt][0], al[mt][1], al[mt][2], al[mt][3], bh0, bh1);
                }
            }
        }
        __syncthreads();
    }

    // ---- C store (fp16) ----
#pragma unroll
    for (int mt = 0; mt < 2; mt++) {
        int row0 = m0c + wm0 + mt * 16 + lq;
#pragma unroll
        for (int nt = 0; nt < 8; nt++) {
            int col = n0c + wn0 + nt * 8 + 2 * lr;
            if (row0 < NN)
                *(__half2*)(C + (size_t)row0 * FO + col) =
                    __floats2half2_rn(acc[mt][nt][0], acc[mt][nt][1]);
            if (row0 + 8 < NN)
                *(__half2*)(C + (size_t)(row0 + 8) * FO + col) =
                    __floats2half2_rn(acc[mt][nt][2], acc[mt][nt][3]);
        }
    }

    // ---- fused alpha_src / alpha_dst ----
    {
        int h = (n0c + wn0) >> 6;
        float ps0 = 0.f, ps1 = 0.f, ps2 = 0.f, ps3 = 0.f;
        float pd0 = 0.f, pd1 = 0.f, pd2 = 0.f, pd3 = 0.f;
#pragma unroll
        for (int nt = 0; nt < 8; nt++) {
            int c0 = nt * 8 + 2 * lr;
            float2 cs = *(const float2*)(asrc + h * 64 + c0);
            float2 cd = *(const float2*)(adst + h * 64 + c0);
            ps0 += acc[0][nt][0] * cs.x + acc[0][nt][1] * cs.y;
            ps1 += acc[0][nt][2] * cs.x + acc[0][nt][3] * cs.y;
            ps2 += acc[1][nt][0] * cs.x + acc[1][nt][1] * cs.y;
            ps3 += acc[1][nt][2] * cs.x + acc[1][nt][3] * cs.y;
            pd0 += acc[0][nt][0] * cd.x + acc[0][nt][1] * cd.y;
            pd1 += acc[0][nt][2] * cd.x + acc[0][nt][3] * cd.y;
            pd2 += acc[1][nt][0] * cd.x + acc[1][nt][1] * cd.y;
            pd3 += acc[1][nt][2] * cd.x + acc[1][nt][3] * cd.y;
        }
#pragma unroll
        for (int o = 1; o <= 2; o <<= 1) {
            ps0 += __shfl_xor_sync(0xffffffffu, ps0, o);
            ps1 += __shfl_xor_sync(0xffffffffu, ps1, o);
            ps2 += __shfl_xor_sync(0xffffffffu, ps2, o);
            ps3 += __shfl_xor_sync(0xffffffffu, ps3, o);
            pd0 += __shfl_xor_sync(0xffffffffu, pd0, o);
            pd1 += __shfl_xor_sync(0xffffffffu, pd1, o);
            pd2 += __shfl_xor_sync(0xffffffffu, pd2, o);
            pd3 += __shfl_xor_sync(0xffffffffu, pd3, o);
        }
        if (lr == 0) {
            int r = m0c + wm0 + lq;
            if (r < NN)      { g_asrc[r * 4 + h] = ps0;        g_adst[r * 4 + h] = pd0; }
            if (r + 8 < NN)  { g_asrc[(r + 8) * 4 + h] = ps1;  g_adst[(r + 8) * 4 + h] = pd1; }
            if (r + 16 < NN) { g_asrc[(r + 16) * 4 + h] = ps2; g_adst[(r + 16) * 4 + h] = pd2; }
            if (r + 24 < NN) { g_asrc[(r + 24) * 4 + h] = ps3; g_adst[(r + 24) * 4 + h] = pd3; }
        }
    }
}

// ================= fused: logits + softmax + fp16 gather, warp per dst ==========
__global__ __launch_bounds__(256) void fused_agg_kernel(
    const float* __restrict__ ce,
    const float* __restrict__ bias,
    float* __restrict__ out_h,
    float* __restrict__ out_w)
{
    __shared__ float s_w[8][32][4];
    __shared__ int   s_s[8][32];
    int wslot = threadIdx.x >> 5;
    int n = blockIdx.x * 8 + wslot;
    int lane = threadIdx.x & 31;
    if (n >= NN) return;
    int r0 = g_rowstart[n], r1 = g_rowstart[n + 1];

    float4 c   = *(const float4*)ce;
    float4 adn = *(const float4*)(g_adst + (size_t)n * 4);

    float4 exA = make_float4(0.f, 0.f, 0.f, 0.f);
    float4 exB = make_float4(0.f, 0.f, 0.f, 0.f);

    // ---- pass 1: logits + leaky relu + max (regs for it<2, global overflow) ----
    float mx0 = -3.4e38f, mx1 = -3.4e38f, mx2 = -3.4e38f, mx3 = -3.4e38f;
    {
        int it = 0;
        for (int i = r0 + lane; i < r1; i += 32, it++) {
            EdgeRec er = g_edge_r[i];
            float4 as = *(const float4*)(g_asrc + (size_t)er.s * 4);
            float a0 = as.x + adn.x + er.ea * c.x;
            float a1 = as.y + adn.y + er.ea * c.y;
            float a2 = as.z + adn.z + er.ea * c.z;
            float a3 = as.w + adn.w + er.ea * c.w;
            a0 = a0 > 0.f ? a0 : NEG_SLOPE * a0;
            a1 = a1 > 0.f ? a1 : NEG_SLOPE * a1;
            a2 = a2 > 0.f ? a2 : NEG_SLOPE * a2;
            a3 = a3 > 0.f ? a3 : NEG_SLOPE * a3;
            if (it == 0)      exA = make_float4(a0, a1, a2, a3);
            else if (it == 1) exB = make_float4(a0, a1, a2, a3);
            else *(float4*)(g_alpha_r + (size_t)i * 4) = make_float4(a0, a1, a2, a3);
            mx0 = fmaxf(mx0, a0); mx1 = fmaxf(mx1, a1);
            mx2 = fmaxf(mx2, a2); mx3 = fmaxf(mx3, a3);
        }
    }
#pragma unroll
    for (int o = 16; o; o >>= 1) {
        mx0 = fmaxf(mx0, __shfl_xor_sync(0xffffffffu, mx0, o));
        mx1 = fmaxf(mx1, __shfl_xor_sync(0xffffffffu, mx1, o));
        mx2 = fmaxf(mx2, __shfl_xor_sync(0xffffffffu, mx2, o));
        mx3 = fmaxf(mx3, __shfl_xor_sync(0xffffffffu, mx3, o));
    }

    // ---- pass 2: exp (in regs / global) + denom ----
    float dn0 = 0.f, dn1 = 0.f, dn2 = 0.f, dn3 = 0.f;
    {
        int it = 0;
        for (int i = r0 + lane; i < r1; i += 32, it++) {
            float4 a = (it == 0) ? exA : (it == 1) ? exB
                                       : *(const float4*)(g_alpha_r + (size_t)i * 4);
            float e0 = __expf(a.x - mx0), e1 = __expf(a.y - mx1);
            float e2 = __expf(a.z - mx2), e3 = __expf(a.w - mx3);
            if (it == 0)      exA = make_float4(e0, e1, e2, e3);
            else if (it == 1) exB = make_float4(e0, e1, e2, e3);
            else *(float4*)(g_alpha_r + (size_t)i * 4) = make_float4(e0, e1, e2, e3);
            dn0 += e0; dn1 += e1; dn2 += e2; dn3 += e3;
        }
    }
#pragma unroll
    for (int o = 16; o; o >>= 1) {
        dn0 += __shfl_xor_sync(0xffffffffu, dn0, o);
        dn1 += __shfl_xor_sync(0xffffffffu, dn1, o);
        dn2 += __shfl_xor_sync(0xffffffffu, dn2, o);
        dn3 += __shfl_xor_sync(0xffffffffu, dn3, o);
    }
    float inv0 = 1.f / (dn0 + 1e-16f);
    float inv1 = 1.f / (dn1 + 1e-16f);
    float inv2 = 1.f / (dn2 + 1e-16f);
    float inv3 = 1.f / (dn3 + 1e-16f);

    // ---- pass 3: weights + fp16 gather with packed f32x2 FMA ----
    int hsel = lane >> 3;
    uint64_t ac0 = pack_f32x2(0.f, 0.f);
    uint64_t ac1 = ac0, ac2 = ac0, ac3 = ac0;

    int chunk = 0;
    for (int base = r0; base < r1; base += 32, chunk++) {
        int i = base + lane;
        int cnt = min(32, r1 - base);
        if (i < r1) {
            float4 ex = (chunk == 0) ? exA : (chunk == 1) ? exB
                                           : *(const float4*)(g_alpha_r + (size_t)i * 4);
            EdgeRec er = g_edge_r[i];
            float w0 = ex.x * inv0, w1 = ex.y * inv1;
            float w2 = ex.z * inv2, w3 = ex.w * inv3;
            *(float4*)(out_w + (size_t)er.e * 4) = make_float4(w0, w1, w2, w3);
            *(float4*)&s_w[wslot][lane][0] =
                make_float4(w0 * er.at, w1 * er.at, w2 * er.at, w3 * er.at);
            s_s[wslot][lane] = er.s;
        }
        __syncwarp();
        for (int j = 0; j < cnt; j++) {
            float w = s_w[wslot][j][hsel];
            uint64_t wp = pack_f32x2(w, w);
            int sc = s_s[wslot][j];
            uint4 v = *((const uint4*)(g_xh + (size_t)sc * FO) + lane);
            float2 f0 = __half22float2(*(__half2*)&v.x);
            float2 f1 = __half22float2(*(__half2*)&v.y);
            float2 f2 = __half22float2(*(__half2*)&v.z);
            float2 f3 = __half22float2(*(__half2*)&v.w);
            uint64_t p0 = pack_f32x2(f0.x, f0.y);
            uint64_t p1 = pack_f32x2(f1.x, f1.y);
            uint64_t p2 = pack_f32x2(f2.x, f2.y);
            uint64_t p3 = pack_f32x2(f3.x, f3.y);
            FMA2(ac0, p0, wp);
            FMA2(ac1, p1, wp);
            FMA2(ac2, p2, wp);
            FMA2(ac3, p3, wp);
        }
        __syncwarp();
    }

    float o0, o1, o2, o3, o4, o5, o6, o7;
    unpack_f32x2(ac0, o0, o1);
    unpack_f32x2(ac1, o2, o3);
    unpack_f32x2(ac2, o4, o5);
    unpack_f32x2(ac3, o6, o7);

    float4 bA = *(const float4*)(bias + lane * 8);
    float4 bB = *(const float4*)(bias + lane * 8 + 4);
    float* orow = out_h + (size_t)n * FO + lane * 8;
    *(float4*)orow = make_float4(o0 + bA.x, o1 + bA.y, o2 + bA.z, o3 + bA.w);
    *(float4*)(orow + 4) = make_float4(o4 + bB.x, o5 + bB.y, o6 + bB.z, o7 + bB.w);
}

// ================= launch =================
// Fork/join stream overlap: edge-CSR chain (default stream) runs concurrently
// with convert_w + gemm1 (side stream). Streams/events are created lazily on
// the FIRST call (the pre-capture correctness run) — no API calls inside
// capture, no device allocations.
static cudaStream_t g_s2 = nullptr;
static cudaEvent_t  g_evFork = nullptr;
static cudaEvent_t  g_evJoin = nullptr;

extern "C" void kernel_launch(void* const* d_in, const int* in_sizes, int n_in,
                              void* d_out, int out_size)
{
    const float* x          = (const float*)d_in[0];
    const int*   edge_index = (const int*)d_in[1];
    const float* edge_attr  = (const float*)d_in[3];
    const float* edge_atten = (const float*)d_in[4];
    const float* W1    = (const float*)d_in[5];
    const float* asrc1 = (const float*)d_in[6];
    const float* adst1 = (const float*)d_in[7];
    const float* We1   = (const float*)d_in[8];
    const float* ae1   = (const float*)d_in[9];
    const float* b1    = (const float*)d_in[10];
    const float* W2    = (const float*)d_in[11];
    const float* asrc2 = (const float*)d_in[12];
    const float* adst2 = (const float*)d_in[13];
    const float* We2   = (const float*)d_in[14];
    const float* ae2   = (const float*)d_in[15];
    const float* b2    = (const float*)d_in[16];

    const int* src = edge_index;
    const int* dst = edge_index + NE;

    float* out    = (float*)d_out;
    float* out_h  = out;
    float* out_w1 = out + (size_t)NN * FO;
    float* out_w2 = out_w1 + (size_t)NE * HD;

    __half* xh;  cudaGetSymbolAddress((void**)&xh, g_xh);
    float* hbuf; cudaGetSymbolAddress((void**)&hbuf, g_h);
    float* ce1;  cudaGetSymbolAddress((void**)&ce1, g_ce1);
    float* ce2;  cudaGetSymbolAddress((void**)&ce2, g_ce2);
    __nv_bfloat16 *wt1h, *wt1l, *wt2h, *wt2l;
    cudaGetSymbolAddress((void**)&wt1h, g_Wt1hi);
    cudaGetSymbolAddress((void**)&wt1l, g_Wt1lo);
    cudaGetSymbolAddress((void**)&wt2h, g_Wt2hi);
    cudaGetSymbolAddress((void**)&wt2l, g_Wt2lo);

    if (g_s2 == nullptr) {
        cudaStreamCreateWithFlags(&g_s2, cudaStreamNonBlocking);
        cudaEventCreateWithFlags(&g_evFork, cudaEventDisableTiming);
        cudaEventCreateWithFlags(&g_evJoin, cudaEventDisableTiming);
    }

    dim3 ggrid((NN + 127) / 128, 2);

    // fork: side stream inherits current position of the main stream
    cudaEventRecord(g_evFork, 0);
    cudaStreamWaitEvent(g_s2, g_evFork, 0);

    // chain A (main stream): edge CSR
    zero_counts_kernel<<<(NN + 255) / 256, 256>>>();
    hist_kernel<<<(NE / 4 + 255) / 256, 256>>>(dst);
    scan_kernel<<<1, 1024>>>(We1, ae1, We2, ae2);
    scatter_kernel<<<(NE / 2 + 255) / 256, 256>>>(src, dst, edge_attr, edge_atten);

    // chain B (side stream): W conversion + GEMM1 (+ alpha dots)
    convert_w_kernel<<<(128 * 256 + 256 * 256 + 255) / 256, 256, 0, g_s2>>>(
        W1, W2, wt1h, wt1l, wt2h, wt2l);
    gemm_mma_kernel<<<ggrid, 256, 0, g_s2>>>(x, wt1h, wt1l, xh, 128, asrc1, adst1);

    // join: main stream waits for chain B
    cudaEventRecord(g_evJoin, g_s2);
    cudaStreamWaitEvent(0, g_evJoin, 0);

    // serial tail on main stream
    fused_agg_kernel<<<(NN + 7) / 8, 256>>>(ce1, b1, hbuf, out_w1);
    gemm_mma_kernel<<<ggrid, 256>>>(hbuf, wt2h, wt2l, xh, 256, asrc2, adst2);
    fused_agg_kernel<<<(NN + 7) / 8, 256>>>(ce2, b2, out_h, out_w2);
}